// round 1
// baseline (speedup 1.0000x reference)
#include <cuda_runtime.h>
#include <cuda_bf16.h>
#include <cstdint>

// Problem shape (fixed by the bench): B=4, H=16, S=2048, D=64
#define S_LEN   2048
#define D_DIM   64
#define BH      64
#define QTILES  32   // 2048 / 64 q-rows per CTA
#define KCHUNKS 32   // 2048 / 64 k-cols per chunk

// Per-64x64-tile mask classification: 0 = all zero, 1 = mixed, 2 = all nonzero
__device__ unsigned char g_mask_flags[QTILES * KCHUNKS];

__global__ void mask_flag_kernel(const int* __restrict__ mask) {
    __shared__ int s_any_zero, s_any_nz;
    if (threadIdx.x == 0) { s_any_zero = 0; s_any_nz = 0; }
    __syncthreads();
    const int tile = blockIdx.x;
    const int qt = tile >> 5, kc = tile & 31;
    int a0 = 0, a1 = 0;
    for (int i = threadIdx.x; i < 64 * 64; i += blockDim.x) {
        int r = i >> 6, c = i & 63;
        int m = mask[(size_t)(qt * 64 + r) * S_LEN + kc * 64 + c];
        if (m == 0) a0 = 1; else a1 = 1;
    }
    if (a0) atomicOr(&s_any_zero, 1);
    if (a1) atomicOr(&s_any_nz, 1);
    __syncthreads();
    if (threadIdx.x == 0)
        g_mask_flags[tile] = (unsigned char)(s_any_zero ? (s_any_nz ? 1 : 0) : 2);
}

__device__ __forceinline__ unsigned f2tf32(float x) {
    unsigned u;
    asm("cvt.rna.tf32.f32 %0, %1;" : "=r"(u) : "f"(x));
    return u;
}

__device__ __forceinline__ void mma_tf32(float c[4], const unsigned a[4],
                                         unsigned b0, unsigned b1) {
    asm volatile(
        "mma.sync.aligned.m16n8k8.row.col.f32.tf32.tf32.f32 "
        "{%0,%1,%2,%3}, {%4,%5,%6,%7}, {%8,%9}, {%0,%1,%2,%3};"
        : "+f"(c[0]), "+f"(c[1]), "+f"(c[2]), "+f"(c[3])
        : "r"(a[0]), "r"(a[1]), "r"(a[2]), "r"(a[3]), "r"(b0), "r"(b1));
}

// 4 warps; warp w owns q-rows [16w, 16w+16) of the CTA's 64-row tile.
// m16n8k8 fragment mapping (PTX ISA):
//  A: a0(g,c) a1(g+8,c) a2(g,c+4) a3(g+8,c+4)   with g=lane>>2, c=lane&3
//  B: b0(row=c, col=g)  b1(row=c+4, col=g)
//  C: c0(g,2c) c1(g,2c+1) c2(g+8,2c) c3(g+8,2c+1)
__global__ __launch_bounds__(128)
void fused_attn_kernel(const float* __restrict__ q, const float* __restrict__ k,
                       const float* __restrict__ v, const int* __restrict__ mask,
                       float* __restrict__ out, float* __restrict__ attn,
                       int has_attn)
{
    // Padding: stride 68 -> b-frag LDS bank = 4g+tig (conflict-free)
    //          stride 72 -> V b-frag LDS bank = 8*tig+g (conflict-free)
    __shared__ float sK[64][68];   // K chunk (tf32 bits); reused as P tile in pass 2
    __shared__ float sV[64][72];   // V chunk (tf32 bits)

    const int tid  = threadIdx.x;
    const int warp = tid >> 5, lane = tid & 31;
    const int g = lane >> 2, tig = lane & 3;
    const int qtile = blockIdx.x, bh = blockIdx.y;
    const int wrow = warp * 16;

    const size_t bh_qkv = (size_t)bh * S_LEN * D_DIM;

    // --- Q fragments in registers (scaled by 1/T = 1/8, tf32), constant over chunks ---
    unsigned aq[8][4];
    {
        const float* qp = q + bh_qkv + (size_t)(qtile * 64 + wrow) * D_DIM;
        #pragma unroll
        for (int kt = 0; kt < 8; ++kt) {
            aq[kt][0] = f2tf32(qp[(size_t)(g)     * D_DIM + kt * 8 + tig]     * 0.125f);
            aq[kt][1] = f2tf32(qp[(size_t)(g + 8) * D_DIM + kt * 8 + tig]     * 0.125f);
            aq[kt][2] = f2tf32(qp[(size_t)(g)     * D_DIM + kt * 8 + tig + 4] * 0.125f);
            aq[kt][3] = f2tf32(qp[(size_t)(g + 8) * D_DIM + kt * 8 + tig + 4] * 0.125f);
        }
    }

    const int grow0 = qtile * 64 + wrow + g;  // global q row for c0/c1 (c2/c3: +8)

    float m0 = -1e30f, m1 = -1e30f, l0 = 0.f, l1 = 0.f;

    // ================= Pass 1: online row max / row sum =================
    for (int kc = 0; kc < KCHUNKS; ++kc) {
        const int flag = g_mask_flags[(qtile << 5) + kc];  // uniform across CTA
        if (flag == 0) continue;                            // fully masked: contributes nothing
        __syncthreads();
        {   // cooperative K chunk load -> smem (tf32-converted)
            const float* kp = k + bh_qkv + (size_t)kc * 64 * D_DIM;
            for (int i = tid; i < 1024; i += 128) {
                int r = i >> 4, c4 = (i & 15) << 2;
                float4 val = *(const float4*)(kp + (size_t)r * D_DIM + c4);
                float* dst = &sK[r][c4];
                dst[0] = __uint_as_float(f2tf32(val.x));
                dst[1] = __uint_as_float(f2tf32(val.y));
                dst[2] = __uint_as_float(f2tf32(val.z));
                dst[3] = __uint_as_float(f2tf32(val.w));
            }
        }
        __syncthreads();

        float c[8][4];
        #pragma unroll
        for (int nt = 0; nt < 8; ++nt) { c[nt][0] = c[nt][1] = c[nt][2] = c[nt][3] = 0.f; }
        #pragma unroll
        for (int kt = 0; kt < 8; ++kt) {
            #pragma unroll
            for (int nt = 0; nt < 8; ++nt) {
                unsigned b0 = __float_as_uint(sK[nt * 8 + g][kt * 8 + tig]);
                unsigned b1 = __float_as_uint(sK[nt * 8 + g][kt * 8 + tig + 4]);
                mma_tf32(c[nt], aq[kt], b0, b1);
            }
        }
        // abs() BEFORE masking (matches reference)
        #pragma unroll
        for (int nt = 0; nt < 8; ++nt) {
            c[nt][0] = fabsf(c[nt][0]); c[nt][1] = fabsf(c[nt][1]);
            c[nt][2] = fabsf(c[nt][2]); c[nt][3] = fabsf(c[nt][3]);
        }
        if (flag == 1) {
            #pragma unroll
            for (int nt = 0; nt < 8; ++nt) {
                int col = kc * 64 + nt * 8 + 2 * tig;
                int2 mv0 = *(const int2*)(mask + (size_t)grow0 * S_LEN + col);
                int2 mv1 = *(const int2*)(mask + (size_t)(grow0 + 8) * S_LEN + col);
                if (mv0.x == 0) c[nt][0] = -1e9f;
                if (mv0.y == 0) c[nt][1] = -1e9f;
                if (mv1.x == 0) c[nt][2] = -1e9f;
                if (mv1.y == 0) c[nt][3] = -1e9f;
            }
        }
        // chunk row max (quad reduce: lanes with equal lane>>2 share rows)
        float cm0 = -1e30f, cm1 = -1e30f;
        #pragma unroll
        for (int nt = 0; nt < 8; ++nt) {
            cm0 = fmaxf(cm0, fmaxf(c[nt][0], c[nt][1]));
            cm1 = fmaxf(cm1, fmaxf(c[nt][2], c[nt][3]));
        }
        cm0 = fmaxf(cm0, __shfl_xor_sync(0xffffffffu, cm0, 1));
        cm0 = fmaxf(cm0, __shfl_xor_sync(0xffffffffu, cm0, 2));
        cm1 = fmaxf(cm1, __shfl_xor_sync(0xffffffffu, cm1, 1));
        cm1 = fmaxf(cm1, __shfl_xor_sync(0xffffffffu, cm1, 2));
        float nm0 = fmaxf(m0, cm0), nm1 = fmaxf(m1, cm1);
        float s0 = 0.f, s1 = 0.f;
        #pragma unroll
        for (int nt = 0; nt < 8; ++nt) {
            s0 += __expf(c[nt][0] - nm0) + __expf(c[nt][1] - nm0);
            s1 += __expf(c[nt][2] - nm1) + __expf(c[nt][3] - nm1);
        }
        s0 += __shfl_xor_sync(0xffffffffu, s0, 1);
        s0 += __shfl_xor_sync(0xffffffffu, s0, 2);
        s1 += __shfl_xor_sync(0xffffffffu, s1, 1);
        s1 += __shfl_xor_sync(0xffffffffu, s1, 2);
        l0 = l0 * __expf(m0 - nm0) + s0;  m0 = nm0;
        l1 = l1 * __expf(m1 - nm1) + s1;  m1 = nm1;
    }

    const float il0 = 1.f / l0, il1 = 1.f / l1;

    // ================= Pass 2: attn write + O = P @ V =================
    float o[8][4];
    #pragma unroll
    for (int nt = 0; nt < 8; ++nt) { o[nt][0] = o[nt][1] = o[nt][2] = o[nt][3] = 0.f; }

    for (int kc = 0; kc < KCHUNKS; ++kc) {
        const int flag = g_mask_flags[(qtile << 5) + kc];
        float* ap0 = has_attn
            ? attn + (size_t)bh * S_LEN * S_LEN + (size_t)grow0 * S_LEN + kc * 64
            : nullptr;
        if (flag == 0) {   // masked tile: attn = 0, no O contribution
            if (has_attn) {
                float2 z = make_float2(0.f, 0.f);
                #pragma unroll
                for (int nt = 0; nt < 8; ++nt) {
                    *(float2*)(ap0 + nt * 8 + 2 * tig) = z;
                    *(float2*)(ap0 + (size_t)8 * S_LEN + nt * 8 + 2 * tig) = z;
                }
            }
            continue;
        }
        __syncthreads();   // previous chunk fully consumed (sK as P, sV)
        {   // cooperative K + V chunk loads (tf32-converted)
            const float* kp = k + bh_qkv + (size_t)kc * 64 * D_DIM;
            const float* vp = v + bh_qkv + (size_t)kc * 64 * D_DIM;
            for (int i = tid; i < 1024; i += 128) {
                int r = i >> 4, c4 = (i & 15) << 2;
                float4 kvv = *(const float4*)(kp + (size_t)r * D_DIM + c4);
                float* dk = &sK[r][c4];
                dk[0] = __uint_as_float(f2tf32(kvv.x));
                dk[1] = __uint_as_float(f2tf32(kvv.y));
                dk[2] = __uint_as_float(f2tf32(kvv.z));
                dk[3] = __uint_as_float(f2tf32(kvv.w));
                float4 vvv = *(const float4*)(vp + (size_t)r * D_DIM + c4);
                float* dv = &sV[r][c4];
                dv[0] = __uint_as_float(f2tf32(vvv.x));
                dv[1] = __uint_as_float(f2tf32(vvv.y));
                dv[2] = __uint_as_float(f2tf32(vvv.z));
                dv[3] = __uint_as_float(f2tf32(vvv.w));
            }
        }
        __syncthreads();

        // Recompute scores
        float c[8][4];
        #pragma unroll
        for (int nt = 0; nt < 8; ++nt) { c[nt][0] = c[nt][1] = c[nt][2] = c[nt][3] = 0.f; }
        #pragma unroll
        for (int kt = 0; kt < 8; ++kt) {
            #pragma unroll
            for (int nt = 0; nt < 8; ++nt) {
                unsigned b0 = __float_as_uint(sK[nt * 8 + g][kt * 8 + tig]);
                unsigned b1 = __float_as_uint(sK[nt * 8 + g][kt * 8 + tig + 4]);
                mma_tf32(c[nt], aq[kt], b0, b1);
            }
        }
        #pragma unroll
        for (int nt = 0; nt < 8; ++nt) {
            c[nt][0] = fabsf(c[nt][0]); c[nt][1] = fabsf(c[nt][1]);
            c[nt][2] = fabsf(c[nt][2]); c[nt][3] = fabsf(c[nt][3]);
        }
        if (flag == 1) {
            #pragma unroll
            for (int nt = 0; nt < 8; ++nt) {
                int col = kc * 64 + nt * 8 + 2 * tig;
                int2 mv0 = *(const int2*)(mask + (size_t)grow0 * S_LEN + col);
                int2 mv1 = *(const int2*)(mask + (size_t)(grow0 + 8) * S_LEN + col);
                if (mv0.x == 0) c[nt][0] = -1e9f;
                if (mv0.y == 0) c[nt][1] = -1e9f;
                if (mv1.x == 0) c[nt][2] = -1e9f;
                if (mv1.y == 0) c[nt][3] = -1e9f;
            }
        }
        // Final normalized probabilities
        #pragma unroll
        for (int nt = 0; nt < 8; ++nt) {
            c[nt][0] = __expf(c[nt][0] - m0) * il0;
            c[nt][1] = __expf(c[nt][1] - m0) * il0;
            c[nt][2] = __expf(c[nt][2] - m1) * il1;
            c[nt][3] = __expf(c[nt][3] - m1) * il1;
        }

        __syncthreads();   // all warps done reading sK (K) before P overwrites it

        // attn store (fp32) + P tile into sK (tf32). Each warp writes/reads ONLY
        // its own 16 rows of sK here, so __syncwarp suffices after the store.
        #pragma unroll
        for (int nt = 0; nt < 8; ++nt) {
            int colb = nt * 8 + 2 * tig;
            if (has_attn) {
                *(float2*)(ap0 + colb) = make_float2(c[nt][0], c[nt][1]);
                *(float2*)(ap0 + (size_t)8 * S_LEN + colb) = make_float2(c[nt][2], c[nt][3]);
            }
            sK[wrow + g][colb]         = __uint_as_float(f2tf32(c[nt][0]));
            sK[wrow + g][colb + 1]     = __uint_as_float(f2tf32(c[nt][1]));
            sK[wrow + g + 8][colb]     = __uint_as_float(f2tf32(c[nt][2]));
            sK[wrow + g + 8][colb + 1] = __uint_as_float(f2tf32(c[nt][3]));
        }
        __syncwarp();

        // O += P @ V
        #pragma unroll
        for (int kt = 0; kt < 8; ++kt) {
            unsigned pa[4];
            pa[0] = __float_as_uint(sK[wrow + g]    [kt * 8 + tig]);
            pa[1] = __float_as_uint(sK[wrow + g + 8][kt * 8 + tig]);
            pa[2] = __float_as_uint(sK[wrow + g]    [kt * 8 + tig + 4]);
            pa[3] = __float_as_uint(sK[wrow + g + 8][kt * 8 + tig + 4]);
            #pragma unroll
            for (int nt = 0; nt < 8; ++nt) {
                unsigned b0 = __float_as_uint(sV[kt * 8 + tig]    [nt * 8 + g]);
                unsigned b1 = __float_as_uint(sV[kt * 8 + tig + 4][nt * 8 + g]);
                mma_tf32(o[nt], pa, b0, b1);
            }
        }
    }

    // ================= Output store =================
    {
        float* op0 = out + bh_qkv + (size_t)grow0 * D_DIM;
        float* op1 = out + bh_qkv + (size_t)(grow0 + 8) * D_DIM;
        #pragma unroll
        for (int nt = 0; nt < 8; ++nt) {
            *(float2*)(op0 + nt * 8 + 2 * tig) = make_float2(o[nt][0], o[nt][1]);
            *(float2*)(op1 + nt * 8 + 2 * tig) = make_float2(o[nt][2], o[nt][3]);
        }
    }
}

extern "C" void kernel_launch(void* const* d_in, const int* in_sizes, int n_in,
                              void* d_out, int out_size) {
    const float* q    = (const float*)d_in[0];
    const float* k    = (const float*)d_in[1];
    const float* v    = (const float*)d_in[2];
    const int*   mask = (const int*)d_in[3];

    float* out = (float*)d_out;
    const long long outN  = (long long)BH * S_LEN * D_DIM;   // 8,388,608
    const long long attnN = (long long)BH * S_LEN * S_LEN;   // 268,435,456
    float* attn = nullptr;
    int has_attn = 0;
    if ((long long)out_size >= outN + attnN) {   // tuple (out, attn) flattened
        attn = out + outN;
        has_attn = 1;
    }

    mask_flag_kernel<<<QTILES * KCHUNKS, 256>>>(mask);
    dim3 grid(QTILES, BH);
    fused_attn_kernel<<<grid, 128>>>(q, k, v, mask, out, attn, has_attn);
}